// round 3
// baseline (speedup 1.0000x reference)
#include <cuda_runtime.h>
#include <cstdint>

#define NB 1024   // batch
#define NT 64     // time steps
#define ND 512    // input dim
#define NH 512    // hidden dim
#define NG 2048   // 4*H (gates)
#define NM 65536  // NB*NT rows of X / Z

#define KC     16           // K chunk per stage
#define SPAD   20           // smem row pitch in words (16B-aligned: 80B)
#define STAGES 4
#define STAGE_WORDS (128 * SPAD)
#define SMEM_BYTES (STAGES * 2 * STAGE_WORDS * 4)   // 81920

// ---------------- static device scratch (no allocations allowed) ----------
__device__ float g_Wt[NG * ND];        // W^T gate-interleaved, tf32 (4MB)
__device__ float g_Rt[NG * NH];        // R^T gate-interleaved, tf32 (4MB)
__device__ float g_Xr[(size_t)NM * ND];// X tf32-rounded (134MB)
__device__ float g_Z[(size_t)NM * NG]; // Z = X@W, gate-interleaved cols (536MB)
__device__ float g_biasp[NG];          // permuted bias
__device__ float g_hbuf[2][NB * NH];   // double-buffered hidden state (tf32-rounded)
__device__ float g_cbuf[NB * NH];      // cell state

__device__ __forceinline__ uint32_t f2tf32(float f) {
    uint32_t r;
    asm("cvt.rna.tf32.f32 %0, %1;" : "=r"(r) : "f"(f));
    return r;
}
__device__ __forceinline__ void cpasync16(void* dst, const void* src) {
    uint32_t d = (uint32_t)__cvta_generic_to_shared(dst);
    asm volatile("cp.async.cg.shared.global [%0], [%1], 16;" :: "r"(d), "l"(src));
}
__device__ __forceinline__ void cp_commit() {
    asm volatile("cp.async.commit_group;");
}
__device__ __forceinline__ void cp_wait2() {
    asm volatile("cp.async.wait_group 2;");
}

__device__ __forceinline__ void mma_tf32(float* c, const uint32_t* a, const uint32_t* b) {
    asm volatile(
        "mma.sync.aligned.m16n8k8.row.col.f32.tf32.tf32.f32 "
        "{%0,%1,%2,%3}, {%4,%5,%6,%7}, {%8,%9}, {%0,%1,%2,%3};\n"
        : "+f"(c[0]), "+f"(c[1]), "+f"(c[2]), "+f"(c[3])
        : "r"(a[0]), "r"(a[1]), "r"(a[2]), "r"(a[3]),
          "r"(b[0]), "r"(b[1]));
}

__device__ __forceinline__ float sigmoidf_(float x) {
    return __fdividef(1.f, 1.f + __expf(-x));
}
__device__ __forceinline__ float tanhf_(float x) {
    return 2.f * sigmoidf_(2.f * x) - 1.f;
}

// ---------------- prep: permute/round weights, round X, zero state --------
// Interleaved col n = h_idx*4 + gate  <->  original col j = gate*512 + h_idx.
__global__ void prep_kernel(const float* __restrict__ x,
                            const float* __restrict__ W,
                            const float* __restrict__ R,
                            const float* __restrict__ bias) {
    int tid = blockIdx.x * blockDim.x + threadIdx.x;
    int nthr = gridDim.x * blockDim.x;
    for (int i = tid; i < NG * ND; i += nthr) {
        int n = i >> 9;          // / 512
        int k = i & 511;
        int j = (n & 3) * NH + (n >> 2);
        g_Wt[i] = __uint_as_float(f2tf32(W[k * NG + j]));
        g_Rt[i] = __uint_as_float(f2tf32(R[k * NG + j]));
    }
    for (size_t i = tid; i < (size_t)NM * ND; i += nthr)
        g_Xr[i] = __uint_as_float(f2tf32(x[i]));
    if (tid < NG) g_biasp[tid] = bias[(tid & 3) * NH + (tid >> 2)];
    for (int i = tid; i < NB * NH; i += nthr) {
        g_hbuf[1][i] = 0.f;      // step 0 reads buffer 1
        g_cbuf[i] = 0.f;
    }
}

// ---------------- shared GEMM building blocks -----------------------------
// CTA tile 128x128, 8 warps (2M x 4N), warp tile 64x32, m16n8k8 fragments.

struct Frag { float acc[4][4][4]; };

__device__ __forceinline__ void issue_tile(uint32_t* sh, int kt, int tid,
                                           const float* __restrict__ Asrc, int abase,
                                           const float* __restrict__ Bsrc, int bbase) {
    int slot = kt & (STAGES - 1);
    uint32_t* As = sh + slot * 2 * STAGE_WORDS;
    uint32_t* Bs = As + STAGE_WORDS;
    int kk = kt * KC;
    #pragma unroll
    for (int i = 0; i < 2; i++) {
        int c = tid + (i << 8);
        int row = c >> 2, kw = (c & 3) << 2;
        cpasync16(As + row * SPAD + kw, Asrc + (size_t)(abase + row) * 512 + kk + kw);
        cpasync16(Bs + row * SPAD + kw, Bsrc + (size_t)(bbase + row) * 512 + kk + kw);
    }
}

__device__ __forceinline__ void compute_stage(uint32_t* sh, int kt,
                                              int wm, int wn, int gid, int tg,
                                              Frag& f) {
    int slot = kt & (STAGES - 1);
    uint32_t* As = sh + slot * 2 * STAGE_WORDS;
    uint32_t* Bs = As + STAGE_WORDS;
    #pragma unroll
    for (int k8 = 0; k8 < KC; k8 += 8) {
        uint32_t a[4][4], b[4][2];
        #pragma unroll
        for (int mf = 0; mf < 4; mf++) {
            int rb = wm + mf * 16;
            a[mf][0] = As[(rb + gid) * SPAD + k8 + tg];
            a[mf][1] = As[(rb + gid + 8) * SPAD + k8 + tg];
            a[mf][2] = As[(rb + gid) * SPAD + k8 + tg + 4];
            a[mf][3] = As[(rb + gid + 8) * SPAD + k8 + tg + 4];
        }
        #pragma unroll
        for (int nf = 0; nf < 4; nf++) {
            int cb = wn + nf * 8;
            b[nf][0] = Bs[(cb + gid) * SPAD + k8 + tg];
            b[nf][1] = Bs[(cb + gid) * SPAD + k8 + tg + 4];
        }
        #pragma unroll
        for (int mf = 0; mf < 4; mf++)
            #pragma unroll
            for (int nf = 0; nf < 4; nf++)
                mma_tf32(f.acc[mf][nf], a[mf], b[nf]);
    }
}

// ---------------- big parallel GEMM: Z = Xr @ Wt^T ------------------------
// M = 65536, N = 2048, K = 512. grid (16, 512).
__global__ __launch_bounds__(256) void zgemm_kernel() {
    extern __shared__ uint32_t sh[];
    const int tid = threadIdx.x;
    const int bm = blockIdx.y * 128;
    const int bn = blockIdx.x * 128;
    const int warp = tid >> 5, lane = tid & 31;
    const int wm = (warp >> 2) * 64, wn = (warp & 3) * 32;
    const int gid = lane >> 2, tg = lane & 3;

    Frag f;
    #pragma unroll
    for (int i = 0; i < 4; i++)
        #pragma unroll
        for (int j = 0; j < 4; j++)
            #pragma unroll
            for (int r = 0; r < 4; r++) f.acc[i][j][r] = 0.f;

    #pragma unroll
    for (int s = 0; s < STAGES - 1; s++) {
        issue_tile(sh, s, tid, g_Xr, bm, g_Wt, bn);
        cp_commit();
    }
    const int NKT = ND / KC;   // 32
    for (int kt = 0; kt < NKT; kt++) {
        cp_wait2();
        __syncthreads();
        if (kt + STAGES - 1 < NKT)
            issue_tile(sh, kt + STAGES - 1, tid, g_Xr, bm, g_Wt, bn);
        cp_commit();
        compute_stage(sh, kt, wm, wn, gid, tg, f);
    }

    // store Z (float2 per fragment row-pair)
    #pragma unroll
    for (int nf = 0; nf < 4; nf++) {
        int n0 = bn + wn + nf * 8 + 2 * tg;
        #pragma unroll
        for (int mf = 0; mf < 4; mf++) {
            int r0 = bm + wm + mf * 16 + gid;
            *(float2*)(g_Z + (size_t)r0 * NG + n0) =
                make_float2(f.acc[mf][nf][0], f.acc[mf][nf][1]);
            *(float2*)(g_Z + (size_t)(r0 + 8) * NG + n0) =
                make_float2(f.acc[mf][nf][2], f.acc[mf][nf][3]);
        }
    }
}

// ---------------- recurrent step: z = Z[:,t] + h @ Rt^T, LSTM epilogue ----
// grid (16, 8). K = 512.
__global__ __launch_bounds__(256) void lstm_step(float* __restrict__ out, int t) {
    extern __shared__ uint32_t sh[];
    const float* __restrict__ hsrc = g_hbuf[(t + 1) & 1];
    float* __restrict__ hdst = g_hbuf[t & 1];

    const int tid = threadIdx.x;
    const int bm = blockIdx.y * 128;
    const int bn = blockIdx.x * 128;
    const int warp = tid >> 5, lane = tid & 31;
    const int wm = (warp >> 2) * 64, wn = (warp & 3) * 32;
    const int gid = lane >> 2, tg = lane & 3;

    Frag f;
    #pragma unroll
    for (int i = 0; i < 4; i++)
        #pragma unroll
        for (int j = 0; j < 4; j++)
            #pragma unroll
            for (int r = 0; r < 4; r++) f.acc[i][j][r] = 0.f;

    #pragma unroll
    for (int s = 0; s < STAGES - 1; s++) {
        issue_tile(sh, s, tid, hsrc, bm, g_Rt, bn);
        cp_commit();
    }
    const int NKT = NH / KC;   // 32
    for (int kt = 0; kt < NKT; kt++) {
        cp_wait2();
        __syncthreads();
        if (kt + STAGES - 1 < NKT)
            issue_tile(sh, kt + STAGES - 1, tid, hsrc, bm, g_Rt, bn);
        cp_commit();
        compute_stage(sh, kt, wm, wn, gid, tg, f);
    }

    // ---- fused LSTM epilogue: z = acc + Z + bias, gates via shfl_xor(1) ----
    const bool evn = (lane & 1) == 0;
    #pragma unroll
    for (int nf = 0; nf < 4; nf++) {
        int nblk = bn + wn + nf * 8;
        int n0 = nblk + 2 * tg;
        float b0 = g_biasp[n0];
        float b1 = g_biasp[n0 + 1];
        int hidx = (nblk >> 2) + (tg >> 1);
        #pragma unroll
        for (int mf = 0; mf < 4; mf++) {
            int r0 = bm + wm + mf * 16 + gid;
            #pragma unroll
            for (int hh = 0; hh < 2; hh++) {
                int brow = r0 + hh * 8;
                float2 zv = *(const float2*)(g_Z + ((size_t)brow * NT + t) * NG + n0);
                float v0 = f.acc[mf][nf][hh * 2 + 0] + zv.x + b0;
                float v1 = f.acc[mf][nf][hh * 2 + 1] + zv.y + b1;
                float p0 = __shfl_xor_sync(0xffffffffu, v0, 1);
                float p1 = __shfl_xor_sync(0xffffffffu, v1, 1);
                if (evn) {
                    float iv = sigmoidf_(v0);
                    float fv = sigmoidf_(v1);
                    float gv = tanhf_(p0);
                    float ov = sigmoidf_(p1);
                    int ci = brow * NH + hidx;
                    float cn = fv * g_cbuf[ci] + iv * gv;
                    float hn = ov * tanhf_(cn);
                    g_cbuf[ci] = cn;
                    hdst[ci] = __uint_as_float(f2tf32(hn));  // tf32 for next-step MMA
                    out[(size_t)brow * (NT * NH) + (size_t)t * NH + hidx] = hn;
                }
            }
        }
    }
}

extern "C" void kernel_launch(void* const* d_in, const int* in_sizes, int n_in,
                              void* d_out, int out_size) {
    const float* x    = (const float*)d_in[0]; // input_context [1024,64,512]
    const float* W    = (const float*)d_in[1]; // kernel [512,2048]
    const float* R    = (const float*)d_in[2]; // recurrent_kernel [512,2048]
    const float* bias = (const float*)d_in[3]; // bias [2048]
    float* out = (float*)d_out;                // [1024,64,512]

    cudaFuncSetAttribute(zgemm_kernel, cudaFuncAttributeMaxDynamicSharedMemorySize, SMEM_BYTES);
    cudaFuncSetAttribute(lstm_step,   cudaFuncAttributeMaxDynamicSharedMemorySize, SMEM_BYTES);

    prep_kernel<<<512, 256>>>(x, W, R, bias);
    zgemm_kernel<<<dim3(16, 512), 256, SMEM_BYTES>>>();
    for (int t = 0; t < NT; t++)
        lstm_step<<<dim3(16, 8), 256, SMEM_BYTES>>>(out, t);
}

// round 4
// speedup vs baseline: 1.9019x; 1.9019x over previous
#include <cuda_runtime.h>
#include <cstdint>

#define NB 1024   // batch
#define NT 64     // time steps
#define ND 512    // input dim
#define NH 512    // hidden dim
#define NG 2048   // 4*H (gates)
#define NM 65536  // NB*NT rows of X / Z

#define KC     32           // K chunk per stage
#define SPAD   36           // smem row pitch in words (conflict-free, 16B-aligned)
#define STAGES 3

// ---------------- static device scratch (no allocations allowed) ----------
__device__ float g_Wt[NG * ND];        // W^T gate-interleaved, tf32 (4MB)
__device__ float g_Rt[NG * NH];        // R^T gate-interleaved, tf32 (4MB)
__device__ float g_Z[(size_t)NM * NG]; // Z = X@W + bias, interleaved cols (536MB)
__device__ float g_biasp[NG];          // permuted bias
__device__ float g_hbuf[2][NB * NH];   // double-buffered hidden state (tf32-rounded)
__device__ float g_cbuf[NB * NH];      // cell state

__device__ __forceinline__ uint32_t f2tf32(float f) {
    uint32_t r;
    asm("cvt.rna.tf32.f32 %0, %1;" : "=r"(r) : "f"(f));
    return r;
}
__device__ __forceinline__ void cpasync16(void* dst, const void* src) {
    uint32_t d = (uint32_t)__cvta_generic_to_shared(dst);
    asm volatile("cp.async.cg.shared.global [%0], [%1], 16;" :: "r"(d), "l"(src));
}
__device__ __forceinline__ void cp_commit() {
    asm volatile("cp.async.commit_group;");
}
__device__ __forceinline__ void cp_wait1() {
    asm volatile("cp.async.wait_group 1;");
}

__device__ __forceinline__ void mma_tf32(float* c, const uint32_t* a, const uint32_t* b) {
    asm volatile(
        "mma.sync.aligned.m16n8k8.row.col.f32.tf32.tf32.f32 "
        "{%0,%1,%2,%3}, {%4,%5,%6,%7}, {%8,%9}, {%0,%1,%2,%3};\n"
        : "+f"(c[0]), "+f"(c[1]), "+f"(c[2]), "+f"(c[3])
        : "r"(a[0]), "r"(a[1]), "r"(a[2]), "r"(a[3]),
          "r"(b[0]), "r"(b[1]));
}

__device__ __forceinline__ float sigmoidf_(float x) {
    return __fdividef(1.f, 1.f + __expf(-x));
}
__device__ __forceinline__ float tanhf_(float x) {
    return 2.f * sigmoidf_(2.f * x) - 1.f;
}

// ---------------- prep: permute/round weights, zero state -----------------
// Interleaved col n = h_idx*4 + gate  <->  original col j = gate*512 + h_idx.
__global__ void prep_kernel(const float* __restrict__ W,
                            const float* __restrict__ R,
                            const float* __restrict__ bias) {
    int tid = blockIdx.x * blockDim.x + threadIdx.x;
    int nthr = gridDim.x * blockDim.x;
    for (int i = tid; i < NG * ND; i += nthr) {
        int n = i >> 9;          // / 512
        int k = i & 511;
        int j = (n & 3) * NH + (n >> 2);
        g_Wt[i] = __uint_as_float(f2tf32(W[k * NG + j]));
        g_Rt[i] = __uint_as_float(f2tf32(R[k * NG + j]));
    }
    if (tid < NG) g_biasp[tid] = bias[(tid & 3) * NH + (tid >> 2)];
    for (int i = tid; i < NB * NH; i += nthr) {
        g_hbuf[1][i] = 0.f;      // step 0 reads buffer 1
        g_cbuf[i] = 0.f;
    }
}

// ---------------- shared GEMM building blocks -----------------------------
// CTA tile TM x 128, 8 warps (2M x 4N), warp tile (TM/2) x 32, m16n8k8.
// Stage layout: [A: TM*SPAD words][B: 128*SPAD words], k contiguous per row.

template<int TM>
__device__ __forceinline__ void issue_tile(uint32_t* sh, int slot, int kk, int tid,
                                           const float* __restrict__ Asrc, int abase,
                                           const float* __restrict__ Bsrc, int bbase) {
    uint32_t* As = sh + slot * (TM + 128) * SPAD;
    uint32_t* Bs = As + TM * SPAD;
    #pragma unroll
    for (int c = tid; c < TM * 8; c += 256) {          // 8 x 16B chunks per row
        int row = c >> 3, q = (c & 7) << 2;
        cpasync16(As + row * SPAD + q, Asrc + (size_t)(abase + row) * 512 + kk + q);
    }
    #pragma unroll
    for (int c = tid; c < 128 * 8; c += 256) {
        int row = c >> 3, q = (c & 7) << 2;
        cpasync16(Bs + row * SPAD + q, Bsrc + (size_t)(bbase + row) * 512 + kk + q);
    }
}

template<int TM, bool CVTA>
__device__ __forceinline__ void compute_stage(uint32_t* sh, int slot,
                                              int wm, int wn, int gid, int tg,
                                              float acc[][4][4]) {
    constexpr int MF = TM / 32;
    uint32_t* As = sh + slot * (TM + 128) * SPAD;
    uint32_t* Bs = As + TM * SPAD;
    #pragma unroll
    for (int k8 = 0; k8 < KC; k8 += 8) {
        uint32_t a[MF][4], b[4][2];
        #pragma unroll
        for (int mf = 0; mf < MF; mf++) {
            int rb = wm + mf * 16;
            a[mf][0] = As[(rb + gid) * SPAD + k8 + tg];
            a[mf][1] = As[(rb + gid + 8) * SPAD + k8 + tg];
            a[mf][2] = As[(rb + gid) * SPAD + k8 + tg + 4];
            a[mf][3] = As[(rb + gid + 8) * SPAD + k8 + tg + 4];
            if (CVTA) {
                #pragma unroll
                for (int r = 0; r < 4; r++)
                    a[mf][r] = f2tf32(__uint_as_float(a[mf][r]));
            }
        }
        #pragma unroll
        for (int nf = 0; nf < 4; nf++) {
            int cb = wn + nf * 8;
            b[nf][0] = Bs[(cb + gid) * SPAD + k8 + tg];
            b[nf][1] = Bs[(cb + gid) * SPAD + k8 + tg + 4];
        }
        #pragma unroll
        for (int mf = 0; mf < MF; mf++)
            #pragma unroll
            for (int nf = 0; nf < 4; nf++)
                mma_tf32(acc[mf][nf], a[mf], b[nf]);
    }
}

// ---------------- big parallel GEMM: Z = tf32(X) @ Wt^T + bias ------------
// M = 65536 (rows are (b,t)), N = 2048, K = 512. grid (16, 512), 128x128 tile.
#define ZSMEM (STAGES * (128 + 128) * SPAD * 4)   // 110592
__global__ __launch_bounds__(256, 2) void zgemm_kernel(const float* __restrict__ x) {
    extern __shared__ uint32_t sh[];
    const int tid = threadIdx.x;
    const int bm = blockIdx.y * 128;
    const int bn = blockIdx.x * 128;
    const int warp = tid >> 5, lane = tid & 31;
    const int wm = (warp >> 2) * 64, wn = (warp & 3) * 32;
    const int gid = lane >> 2, tg = lane & 3;

    float acc[4][4][4];
    #pragma unroll
    for (int i = 0; i < 4; i++)
        #pragma unroll
        for (int j = 0; j < 4; j++)
            #pragma unroll
            for (int r = 0; r < 4; r++) acc[i][j][r] = 0.f;

    issue_tile<128>(sh, 0, 0, tid, x, bm, g_Wt, bn); cp_commit();
    issue_tile<128>(sh, 1, KC, tid, x, bm, g_Wt, bn); cp_commit();

    const int NKT = ND / KC;   // 16
    for (int kt = 0; kt < NKT; kt++) {
        cp_wait1();
        __syncthreads();
        if (kt + 2 < NKT)
            issue_tile<128>(sh, (kt + 2) % STAGES, (kt + 2) * KC, tid, x, bm, g_Wt, bn);
        cp_commit();
        compute_stage<128, true>(sh, kt % STAGES, wm, wn, gid, tg, acc);
        __syncthreads();
    }

    // store Z with bias folded in
    #pragma unroll
    for (int nf = 0; nf < 4; nf++) {
        int n0 = bn + wn + nf * 8 + 2 * tg;
        float2 bb = *(const float2*)(g_biasp + n0);
        #pragma unroll
        for (int mf = 0; mf < 4; mf++) {
            int r0 = bm + wm + mf * 16 + gid;
            *(float2*)(g_Z + (size_t)r0 * NG + n0) =
                make_float2(acc[mf][nf][0] + bb.x, acc[mf][nf][1] + bb.y);
            *(float2*)(g_Z + (size_t)(r0 + 8) * NG + n0) =
                make_float2(acc[mf][nf][2] + bb.x, acc[mf][nf][3] + bb.y);
        }
    }
}

// ---------------- recurrent step: z = Z[:,t] + h @ Rt^T, LSTM epilogue ----
// CTA tile 64(M) x 128(N), grid (16, 16) = 256 CTAs, 2 per SM. K = 512.
#define LSMEM (STAGES * (64 + 128) * SPAD * 4)    // 82944
__global__ __launch_bounds__(256, 2) void lstm_step(float* __restrict__ out, int t) {
    extern __shared__ uint32_t sh[];
    const float* __restrict__ hsrc = g_hbuf[(t + 1) & 1];
    float* __restrict__ hdst = g_hbuf[t & 1];

    const int tid = threadIdx.x;
    const int bm = blockIdx.y * 64;
    const int bn = blockIdx.x * 128;
    const int warp = tid >> 5, lane = tid & 31;
    const int wm = (warp >> 2) * 32, wn = (warp & 3) * 32;
    const int gid = lane >> 2, tg = lane & 3;

    float acc[2][4][4];
    #pragma unroll
    for (int i = 0; i < 2; i++)
        #pragma unroll
        for (int j = 0; j < 4; j++)
            #pragma unroll
            for (int r = 0; r < 4; r++) acc[i][j][r] = 0.f;

    issue_tile<64>(sh, 0, 0, tid, hsrc, bm, g_Rt, bn); cp_commit();
    issue_tile<64>(sh, 1, KC, tid, hsrc, bm, g_Rt, bn); cp_commit();

    const int NKT = NH / KC;   // 16
    for (int kt = 0; kt < NKT; kt++) {
        cp_wait1();
        __syncthreads();
        if (kt + 2 < NKT)
            issue_tile<64>(sh, (kt + 2) % STAGES, (kt + 2) * KC, tid, hsrc, bm, g_Rt, bn);
        cp_commit();
        compute_stage<64, false>(sh, kt % STAGES, wm, wn, gid, tg, acc);
        __syncthreads();
    }

    // ---- fused LSTM epilogue (bias already folded into Z) ----
    // Even tg lanes hold gates (i,f), odd hold (g,o) of the same hidden unit.
    const bool evn = (lane & 1) == 0;
    #pragma unroll
    for (int nf = 0; nf < 4; nf++) {
        int nblk = bn + wn + nf * 8;
        int n0 = nblk + 2 * tg;
        int hidx = (nblk >> 2) + (tg >> 1);
        #pragma unroll
        for (int mf = 0; mf < 2; mf++) {
            int r0 = bm + wm + mf * 16 + gid;
            #pragma unroll
            for (int hh = 0; hh < 2; hh++) {
                int brow = r0 + hh * 8;
                float2 zv = *(const float2*)(g_Z + ((size_t)brow * NT + t) * NG + n0);
                float v0 = acc[mf][nf][hh * 2 + 0] + zv.x;
                float v1 = acc[mf][nf][hh * 2 + 1] + zv.y;
                float p0 = __shfl_xor_sync(0xffffffffu, v0, 1);
                float p1 = __shfl_xor_sync(0xffffffffu, v1, 1);
                if (evn) {
                    float iv = sigmoidf_(v0);
                    float fv = sigmoidf_(v1);
                    float gv = tanhf_(p0);
                    float ov = sigmoidf_(p1);
                    int ci = brow * NH + hidx;
                    float cn = fv * g_cbuf[ci] + iv * gv;
                    float hn = ov * tanhf_(cn);
                    g_cbuf[ci] = cn;
                    hdst[ci] = __uint_as_float(f2tf32(hn));  // tf32 for next-step MMA
                    out[(size_t)brow * (NT * NH) + (size_t)t * NH + hidx] = hn;
                }
            }
        }
    }
}

extern "C" void kernel_launch(void* const* d_in, const int* in_sizes, int n_in,
                              void* d_out, int out_size) {
    const float* x    = (const float*)d_in[0]; // input_context [1024,64,512]
    const float* W    = (const float*)d_in[1]; // kernel [512,2048]
    const float* R    = (const float*)d_in[2]; // recurrent_kernel [512,2048]
    const float* bias = (const float*)d_in[3]; // bias [2048]
    float* out = (float*)d_out;                // [1024,64,512]

    cudaFuncSetAttribute(zgemm_kernel, cudaFuncAttributeMaxDynamicSharedMemorySize, ZSMEM);
    cudaFuncSetAttribute(lstm_step,   cudaFuncAttributeMaxDynamicSharedMemorySize, LSMEM);

    prep_kernel<<<512, 256>>>(W, R, bias);
    zgemm_kernel<<<dim3(16, 512), 256, ZSMEM>>>(x);
    for (int t = 0; t < NT; t++)
        lstm_step<<<dim3(16, 16), 256, LSMEM>>>(out, t);
}

// round 6
// speedup vs baseline: 1.9491x; 1.0248x over previous
#include <cuda_runtime.h>
#include <cstdint>

#define NB 1024   // batch
#define NT 64     // time steps
#define ND 512    // input dim
#define NH 512    // hidden dim
#define NG 2048   // 4*H (gates)
#define NM 65536  // NB*NT rows of X / Z

#define KC     32           // K chunk per stage
#define SPAD   36           // smem row pitch in words (conflict-free, 16B-aligned)
#define STAGES 3

// ---------------- static device scratch (no allocations allowed) ----------
__device__ float g_Wt[NG * ND];        // W^T gate-interleaved, tf32 (4MB)
__device__ float g_Rt[NG * NH];        // R^T gate-interleaved, tf32 (4MB)
__device__ float g_Z[(size_t)NM * NG]; // Z = X@W + bias, interleaved cols (536MB)
__device__ float g_biasp[NG];          // permuted bias
__device__ float g_hbuf[2][NB * NH];   // double-buffered hidden state (tf32-rounded)
__device__ float g_cbuf[NB * NH];      // cell state
__device__ int   g_gbar[16];           // per-row-group step barrier counters

__device__ __forceinline__ uint32_t f2tf32(float f) {
    uint32_t r;
    asm("cvt.rna.tf32.f32 %0, %1;" : "=r"(r) : "f"(f));
    return r;
}
__device__ __forceinline__ void cpasync16(void* dst, const void* src) {
    uint32_t d = (uint32_t)__cvta_generic_to_shared(dst);
    asm volatile("cp.async.cg.shared.global [%0], [%1], 16;" :: "r"(d), "l"(src));
}
__device__ __forceinline__ void cp_commit() {
    asm volatile("cp.async.commit_group;");
}
__device__ __forceinline__ void cp_wait1() {
    asm volatile("cp.async.wait_group 1;");
}

__device__ __forceinline__ void mma_tf32(float* c, const uint32_t* a, const uint32_t* b) {
    asm volatile(
        "mma.sync.aligned.m16n8k8.row.col.f32.tf32.tf32.f32 "
        "{%0,%1,%2,%3}, {%4,%5,%6,%7}, {%8,%9}, {%0,%1,%2,%3};\n"
        : "+f"(c[0]), "+f"(c[1]), "+f"(c[2]), "+f"(c[3])
        : "r"(a[0]), "r"(a[1]), "r"(a[2]), "r"(a[3]),
          "r"(b[0]), "r"(b[1]));
}

__device__ __forceinline__ float sigmoidf_(float x) {
    return __fdividef(1.f, 1.f + __expf(-x));
}
__device__ __forceinline__ float tanhf_(float x) {
    return 2.f * sigmoidf_(2.f * x) - 1.f;
}

// ---------------- prep: permute/round weights, zero state -----------------
// Interleaved col n = h_idx*4 + gate  <->  original col j = gate*512 + h_idx.
__global__ void prep_kernel(const float* __restrict__ W,
                            const float* __restrict__ R,
                            const float* __restrict__ bias) {
    int tid = blockIdx.x * blockDim.x + threadIdx.x;
    int nthr = gridDim.x * blockDim.x;
    for (int i = tid; i < NG * ND; i += nthr) {
        int n = i >> 9;          // / 512
        int k = i & 511;
        int j = (n & 3) * NH + (n >> 2);
        g_Wt[i] = __uint_as_float(f2tf32(W[k * NG + j]));
        g_Rt[i] = __uint_as_float(f2tf32(R[k * NG + j]));
    }
    if (tid < NG) g_biasp[tid] = bias[(tid & 3) * NH + (tid >> 2)];
    if (tid < 16) g_gbar[tid] = 0;     // reset step barrier (fresh each replay)
    for (int i = tid; i < NB * NH; i += nthr) {
        g_hbuf[1][i] = 0.f;      // step 0 reads buffer 1
        g_cbuf[i] = 0.f;
    }
}

// ---------------- shared GEMM building blocks -----------------------------
// CTA tile TM x 128, 8 warps (2M x 4N), warp tile (TM/2) x 32, m16n8k8.
// Stage layout: [A: TM*SPAD words][B: 128*SPAD words], k contiguous per row.

template<int TM>
__device__ __forceinline__ void issue_tile(uint32_t* sh, int slot, int kk, int tid,
                                           const float* __restrict__ Asrc, int abase,
                                           const float* __restrict__ Bsrc, int bbase) {
    uint32_t* As = sh + slot * (TM + 128) * SPAD;
    uint32_t* Bs = As + TM * SPAD;
    #pragma unroll
    for (int c = tid; c < TM * 8; c += 256) {          // 8 x 16B chunks per row
        int row = c >> 3, q = (c & 7) << 2;
        cpasync16(As + row * SPAD + q, Asrc + (size_t)(abase + row) * 512 + kk + q);
    }
    #pragma unroll
    for (int c = tid; c < 128 * 8; c += 256) {
        int row = c >> 3, q = (c & 7) << 2;
        cpasync16(Bs + row * SPAD + q, Bsrc + (size_t)(bbase + row) * 512 + kk + q);
    }
}

template<int TM, bool CVTA>
__device__ __forceinline__ void compute_stage(uint32_t* sh, int slot,
                                              int wm, int wn, int gid, int tg,
                                              float acc[][4][4]) {
    constexpr int MF = TM / 32;
    uint32_t* As = sh + slot * (TM + 128) * SPAD;
    uint32_t* Bs = As + TM * SPAD;
    #pragma unroll
    for (int k8 = 0; k8 < KC; k8 += 8) {
        uint32_t a[MF][4], b[4][2];
        #pragma unroll
        for (int mf = 0; mf < MF; mf++) {
            int rb = wm + mf * 16;
            a[mf][0] = As[(rb + gid) * SPAD + k8 + tg];
            a[mf][1] = As[(rb + gid + 8) * SPAD + k8 + tg];
            a[mf][2] = As[(rb + gid) * SPAD + k8 + tg + 4];
            a[mf][3] = As[(rb + gid + 8) * SPAD + k8 + tg + 4];
            if (CVTA) {
                #pragma unroll
                for (int r = 0; r < 4; r++)
                    a[mf][r] = f2tf32(__uint_as_float(a[mf][r]));
            }
        }
        #pragma unroll
        for (int nf = 0; nf < 4; nf++) {
            int cb = wn + nf * 8;
            b[nf][0] = Bs[(cb + gid) * SPAD + k8 + tg];
            b[nf][1] = Bs[(cb + gid) * SPAD + k8 + tg + 4];
        }
        #pragma unroll
        for (int mf = 0; mf < MF; mf++)
            #pragma unroll
            for (int nf = 0; nf < 4; nf++)
                mma_tf32(acc[mf][nf], a[mf], b[nf]);
    }
}

// ---------------- big parallel GEMM: Z = tf32(X) @ Wt^T + bias ------------
// M = 65536 (rows are (b,t)), N = 2048, K = 512. grid (16, 512), 128x128 tile.
#define ZSMEM (STAGES * (128 + 128) * SPAD * 4)   // 110592
__global__ __launch_bounds__(256, 2) void zgemm_kernel(const float* __restrict__ x) {
    extern __shared__ uint32_t sh[];
    const int tid = threadIdx.x;
    const int bm = blockIdx.y * 128;
    const int bn = blockIdx.x * 128;
    const int warp = tid >> 5, lane = tid & 31;
    const int wm = (warp >> 2) * 64, wn = (warp & 3) * 32;
    const int gid = lane >> 2, tg = lane & 3;

    float acc[4][4][4];
    #pragma unroll
    for (int i = 0; i < 4; i++)
        #pragma unroll
        for (int j = 0; j < 4; j++)
            #pragma unroll
            for (int r = 0; r < 4; r++) acc[i][j][r] = 0.f;

    issue_tile<128>(sh, 0, 0, tid, x, bm, g_Wt, bn); cp_commit();
    issue_tile<128>(sh, 1, KC, tid, x, bm, g_Wt, bn); cp_commit();

    const int NKT = ND / KC;   // 16
    for (int kt = 0; kt < NKT; kt++) {
        cp_wait1();
        __syncthreads();
        if (kt + 2 < NKT)
            issue_tile<128>(sh, (kt + 2) % STAGES, (kt + 2) * KC, tid, x, bm, g_Wt, bn);
        cp_commit();
        compute_stage<128, true>(sh, kt % STAGES, wm, wn, gid, tg, acc);
    }

    // store Z with bias folded in
    #pragma unroll
    for (int nf = 0; nf < 4; nf++) {
        int n0 = bn + wn + nf * 8 + 2 * tg;
        float2 bb = *(const float2*)(g_biasp + n0);
        #pragma unroll
        for (int mf = 0; mf < 4; mf++) {
            int r0 = bm + wm + mf * 16 + gid;
            *(float2*)(g_Z + (size_t)r0 * NG + n0) =
                make_float2(acc[mf][nf][0] + bb.x, acc[mf][nf][1] + bb.y);
            *(float2*)(g_Z + (size_t)(r0 + 8) * NG + n0) =
                make_float2(acc[mf][nf][2] + bb.x, acc[mf][nf][3] + bb.y);
        }
    }
}

// ---------------- persistent recurrence: all 64 steps in one kernel -------
// CTA tile 64(M) x 128(N), grid (16 bn, 16 bm) = 256 CTAs, 2/SM (all resident:
// 256 <= 296 capacity). Row-group bm = 16 CTAs; only they exchange h -> per-
// group atomic barrier between steps instead of kernel relaunch.
#define LSMEM (STAGES * (64 + 128) * SPAD * 4)    // 82944
__global__ __launch_bounds__(256, 2) void lstm_persist(float* __restrict__ out) {
    extern __shared__ uint32_t sh[];
    const int tid = threadIdx.x;
    const int grp = blockIdx.y;
    const int bm = blockIdx.y * 64;
    const int bn = blockIdx.x * 128;
    const int warp = tid >> 5, lane = tid & 31;
    const int wm = (warp >> 2) * 32, wn = (warp & 3) * 32;
    const int gid = lane >> 2, tg = lane & 3;
    const bool evn = (lane & 1) == 0;

    #pragma unroll 1
    for (int t = 0; t < NT; t++) {
        const float* __restrict__ hsrc = g_hbuf[(t + 1) & 1];
        float* __restrict__ hdst = g_hbuf[t & 1];

        float acc[2][4][4];
        #pragma unroll
        for (int i = 0; i < 2; i++)
            #pragma unroll
            for (int j = 0; j < 4; j++)
                #pragma unroll
                for (int r = 0; r < 4; r++) acc[i][j][r] = 0.f;

        issue_tile<64>(sh, 0, 0, tid, hsrc, bm, g_Rt, bn); cp_commit();
        issue_tile<64>(sh, 1, KC, tid, hsrc, bm, g_Rt, bn); cp_commit();

        const int NKT = NH / KC;   // 16
        for (int kt = 0; kt < NKT; kt++) {
            cp_wait1();
            __syncthreads();
            if (kt + 2 < NKT)
                issue_tile<64>(sh, (kt + 2) % STAGES, (kt + 2) * KC, tid, hsrc, bm, g_Rt, bn);
            cp_commit();
            compute_stage<64, false>(sh, kt % STAGES, wm, wn, gid, tg, acc);
        }

        // ---- fused LSTM epilogue (bias already folded into Z) ----
        #pragma unroll
        for (int nf = 0; nf < 4; nf++) {
            int nblk = bn + wn + nf * 8;
            int n0 = nblk + 2 * tg;
            int hidx = (nblk >> 2) + (tg >> 1);
            #pragma unroll
            for (int mf = 0; mf < 2; mf++) {
                int r0 = bm + wm + mf * 16 + gid;
                #pragma unroll
                for (int hh = 0; hh < 2; hh++) {
                    int brow = r0 + hh * 8;
                    float2 zv = *(const float2*)(g_Z + ((size_t)brow * NT + t) * NG + n0);
                    float v0 = acc[mf][nf][hh * 2 + 0] + zv.x;
                    float v1 = acc[mf][nf][hh * 2 + 1] + zv.y;
                    float p0 = __shfl_xor_sync(0xffffffffu, v0, 1);
                    float p1 = __shfl_xor_sync(0xffffffffu, v1, 1);
                    if (evn) {
                        float iv = sigmoidf_(v0);
                        float fv = sigmoidf_(v1);
                        float gv = tanhf_(p0);
                        float ov = sigmoidf_(p1);
                        int ci = brow * NH + hidx;
                        float cn = fv * g_cbuf[ci] + iv * gv;
                        float hn = ov * tanhf_(cn);
                        g_cbuf[ci] = cn;
                        hdst[ci] = __uint_as_float(f2tf32(hn));  // tf32 for next-step MMA
                        out[(size_t)brow * (NT * NH) + (size_t)t * NH + hidx] = hn;
                    }
                }
            }
        }

        // ---- per-group step barrier (16 CTAs share this bm) ----
        if (t < NT - 1) {
            __threadfence();          // release h/c writes device-wide
            __syncthreads();          // all threads' writes + fences done
            if (tid == 0) {
                atomicAdd(&g_gbar[grp], 1);
                int target = 16 * (t + 1);        // monotonic, no reset race
                while (*(volatile int*)&g_gbar[grp] < target) { }
                __threadfence();      // acquire peers' h writes
            }
            __syncthreads();
        }
    }
}

extern "C" void kernel_launch(void* const* d_in, const int* in_sizes, int n_in,
                              void* d_out, int out_size) {
    const float* x    = (const float*)d_in[0]; // input_context [1024,64,512]
    const float* W    = (const float*)d_in[1]; // kernel [512,2048]
    const float* R    = (const float*)d_in[2]; // recurrent_kernel [512,2048]
    const float* bias = (const float*)d_in[3]; // bias [2048]
    float* out = (float*)d_out;                // [1024,64,512]

    cudaFuncSetAttribute(zgemm_kernel, cudaFuncAttributeMaxDynamicSharedMemorySize, ZSMEM);
    cudaFuncSetAttribute(lstm_persist, cudaFuncAttributeMaxDynamicSharedMemorySize, LSMEM);

    prep_kernel<<<512, 256>>>(W, R, bias);
    zgemm_kernel<<<dim3(16, 512), 256, ZSMEM>>>(x);
    lstm_persist<<<dim3(16, 16), 256, LSMEM>>>(out);
}

// round 9
// speedup vs baseline: 2.1440x; 1.1000x over previous
#include <cuda_runtime.h>
#include <cstdint>

#define NB 1024   // batch
#define NT 64     // time steps
#define ND 512    // input dim
#define NH 512    // hidden dim
#define NG 2048   // 4*H (gates)
#define NM 65536  // NB*NT rows of X / Z

#define KC     32           // K chunk per stage
#define SPAD   36           // smem row pitch in words (2-way worst, 16B-aligned)
#define ZSTAGES 3           // zgemm pipeline depth
#define LSTAGES 4           // lstm pipeline depth (4th slot = cross-barrier B prefetch)

// ---------------- static device scratch (no allocations allowed) ----------
__device__ float g_Wt[NG * ND];        // W^T gate-interleaved, tf32 (4MB)
__device__ float g_Rt[NG * NH];        // R^T gate-interleaved, tf32 (4MB)
__device__ float g_Z[(size_t)NM * NG]; // Z = X@W + bias, interleaved cols (536MB)
__device__ float g_biasp[NG];          // permuted bias
__device__ float g_hbuf[2][NB * NH];   // double-buffered hidden state (tf32-rounded)
__device__ float g_cbuf[NB * NH];      // cell state
__device__ int   g_gbar[16];           // per-row-group step barrier counters

__device__ __forceinline__ uint32_t f2tf32(float f) {
    uint32_t r;
    asm("cvt.rna.tf32.f32 %0, %1;" : "=r"(r) : "f"(f));
    return r;
}
__device__ __forceinline__ void cpasync16(void* dst, const void* src) {
    uint32_t d = (uint32_t)__cvta_generic_to_shared(dst);
    asm volatile("cp.async.cg.shared.global [%0], [%1], 16;" :: "r"(d), "l"(src));
}
__device__ __forceinline__ void cp_commit() {
    asm volatile("cp.async.commit_group;");
}
__device__ __forceinline__ void cp_wait1() {
    asm volatile("cp.async.wait_group 1;");
}

__device__ __forceinline__ void mma_tf32(float* c, const uint32_t* a, const uint32_t* b) {
    asm volatile(
        "mma.sync.aligned.m16n8k8.row.col.f32.tf32.tf32.f32 "
        "{%0,%1,%2,%3}, {%4,%5,%6,%7}, {%8,%9}, {%0,%1,%2,%3};\n"
        : "+f"(c[0]), "+f"(c[1]), "+f"(c[2]), "+f"(c[3])
        : "r"(a[0]), "r"(a[1]), "r"(a[2]), "r"(a[3]),
          "r"(b[0]), "r"(b[1]));
}

__device__ __forceinline__ float sigmoidf_(float x) {
    return __fdividef(1.f, 1.f + __expf(-x));
}
__device__ __forceinline__ float tanhf_(float x) {
    return 2.f * sigmoidf_(2.f * x) - 1.f;
}

// ---------------- prep: permute/round weights, zero state -----------------
// Interleaved col n = h_idx*4 + gate  <->  original col j = gate*512 + h_idx.
__global__ void prep_kernel(const float* __restrict__ W,
                            const float* __restrict__ R,
                            const float* __restrict__ bias) {
    int tid = blockIdx.x * blockDim.x + threadIdx.x;
    int nthr = gridDim.x * blockDim.x;
    for (int i = tid; i < NG * ND; i += nthr) {
        int n = i >> 9;          // / 512
        int k = i & 511;
        int j = (n & 3) * NH + (n >> 2);
        g_Wt[i] = __uint_as_float(f2tf32(W[k * NG + j]));
        g_Rt[i] = __uint_as_float(f2tf32(R[k * NG + j]));
    }
    if (tid < NG) g_biasp[tid] = bias[(tid & 3) * NH + (tid >> 2)];
    if (tid < 16) g_gbar[tid] = 0;     // reset step barrier (fresh each replay)
    for (int i = tid; i < NB * NH; i += nthr) {
        g_hbuf[1][i] = 0.f;      // step 0 reads buffer 1
        g_cbuf[i] = 0.f;
    }
}

// ---------------- big parallel GEMM: Z = tf32(X) @ Wt^T + bias ------------
// M = 65536 (rows are (b,t)), N = 2048, K = 512. grid (16, 512), 128x128 tile.
#define ZSMEM (ZSTAGES * (128 + 128) * SPAD * 4)   // 110592

__device__ __forceinline__ void z_issue(uint32_t* sh, int slot, int kk, int tid,
                                        const float* __restrict__ x, int bm, int bn) {
    uint32_t* As = sh + slot * (128 + 128) * SPAD;
    uint32_t* Bs = As + 128 * SPAD;
    #pragma unroll
    for (int c = tid; c < 128 * 8; c += 256) {
        int row = c >> 3, q = (c & 7) << 2;
        cpasync16(As + row * SPAD + q, x + (size_t)(bm + row) * 512 + kk + q);
        cpasync16(Bs + row * SPAD + q, g_Wt + (size_t)(bn + row) * 512 + kk + q);
    }
}

__global__ __launch_bounds__(256, 2) void zgemm_kernel(const float* __restrict__ x) {
    extern __shared__ uint32_t sh[];
    const int tid = threadIdx.x;
    const int bm = blockIdx.y * 128;
    const int bn = blockIdx.x * 128;
    const int warp = tid >> 5, lane = tid & 31;
    const int wm = (warp >> 2) * 64, wn = (warp & 3) * 32;
    const int gid = lane >> 2, tg = lane & 3;

    float acc[4][4][4];
    #pragma unroll
    for (int i = 0; i < 4; i++)
        #pragma unroll
        for (int j = 0; j < 4; j++)
            #pragma unroll
            for (int r = 0; r < 4; r++) acc[i][j][r] = 0.f;

    z_issue(sh, 0, 0, tid, x, bm, bn); cp_commit();
    z_issue(sh, 1, KC, tid, x, bm, bn); cp_commit();

    const int NKT = ND / KC;   // 16
    for (int kt = 0; kt < NKT; kt++) {
        cp_wait1();
        __syncthreads();
        if (kt + 2 < NKT)
            z_issue(sh, (kt + 2) % ZSTAGES, (kt + 2) * KC, tid, x, bm, bn);
        cp_commit();
        // compute slot kt % ZSTAGES
        uint32_t* As = sh + (kt % ZSTAGES) * (128 + 128) * SPAD;
        uint32_t* Bs = As + 128 * SPAD;
        #pragma unroll
        for (int k8 = 0; k8 < KC; k8 += 8) {
            uint32_t a[4][4], b[4][2];
            #pragma unroll
            for (int mf = 0; mf < 4; mf++) {
                int rb = wm + mf * 16;
                a[mf][0] = f2tf32(__uint_as_float(As[(rb + gid) * SPAD + k8 + tg]));
                a[mf][1] = f2tf32(__uint_as_float(As[(rb + gid + 8) * SPAD + k8 + tg]));
                a[mf][2] = f2tf32(__uint_as_float(As[(rb + gid) * SPAD + k8 + tg + 4]));
                a[mf][3] = f2tf32(__uint_as_float(As[(rb + gid + 8) * SPAD + k8 + tg + 4]));
            }
            #pragma unroll
            for (int nf = 0; nf < 4; nf++) {
                int cb = wn + nf * 8;
                b[nf][0] = Bs[(cb + gid) * SPAD + k8 + tg];
                b[nf][1] = Bs[(cb + gid) * SPAD + k8 + tg + 4];
            }
            #pragma unroll
            for (int mf = 0; mf < 4; mf++)
                #pragma unroll
                for (int nf = 0; nf < 4; nf++)
                    mma_tf32(acc[mf][nf], a[mf], b[nf]);
        }
    }

    // store Z with bias folded in
    #pragma unroll
    for (int nf = 0; nf < 4; nf++) {
        int n0 = bn + wn + nf * 8 + 2 * tg;
        float2 bb = *(const float2*)(g_biasp + n0);
        #pragma unroll
        for (int mf = 0; mf < 4; mf++) {
            int r0 = bm + wm + mf * 16 + gid;
            *(float2*)(g_Z + (size_t)r0 * NG + n0) =
                make_float2(acc[mf][nf][0] + bb.x, acc[mf][nf][1] + bb.y);
            *(float2*)(g_Z + (size_t)(r0 + 8) * NG + n0) =
                make_float2(acc[mf][nf][2] + bb.x, acc[mf][nf][3] + bb.y);
        }
    }
}

// ---------------- persistent recurrence: all 64 steps in one kernel -------
// CTA tile 128(M) x 128(N), grid (16 bn, 8 bm) = 128 CTAs, 1/SM (210KB smem),
// 512 threads (16 warps: 4M x 4N, warp tile 32x32, MF=2). cp.async pipeline
// (issue distance 2, wait1 => slot kt drained at iteration kt), Z-tile smem
// prefetch, next-step B prefetch into slots 0/1 before the group barrier.
#define LSTAGE_WORDS ((128 + 128) * SPAD)          // 9216
#define LZOFF (LSTAGES * LSTAGE_WORDS)             // Z region word offset
#define LZPITCH 132                                // Z smem row pitch (words)
#define LSMEM ((LZOFF + 128 * LZPITCH) * 4)        // 215040 bytes

__global__ __launch_bounds__(512, 1) void lstm_persist(float* __restrict__ out) {
    extern __shared__ uint32_t sh[];
    const int tid = threadIdx.x;
    const int grp = blockIdx.y;
    const int bm = blockIdx.y * 128;
    const int bn = blockIdx.x * 128;
    const int warp = tid >> 5, lane = tid & 31;
    const int wm = (warp >> 2) * 32, wn = (warp & 3) * 32;
    const int gid = lane >> 2, tg = lane & 3;
    const bool evn = (lane & 1) == 0;

    // ---- cp.async helpers ----
    auto issueA = [&](int slot, int kk, const float* __restrict__ hsrc) {
        uint32_t* As = sh + slot * LSTAGE_WORDS;
        #pragma unroll
        for (int c = tid; c < 128 * 8; c += 512) {
            int row = c >> 3, q = (c & 7) << 2;
            cpasync16(As + row * SPAD + q, hsrc + (bm + row) * NH + kk + q);
        }
    };
    auto issueB = [&](int slot, int kk) {
        uint32_t* Bs = sh + slot * LSTAGE_WORDS + 128 * SPAD;
        #pragma unroll
        for (int c = tid; c < 128 * 8; c += 512) {
            int row = c >> 3, q = (c & 7) << 2;
            cpasync16(Bs + row * SPAD + q, g_Rt + (size_t)(bn + row) * NH + kk + q);
        }
    };
    auto issueZ = [&](int t) {
        uint32_t* Zs = sh + LZOFF;
        #pragma unroll
        for (int c = tid; c < 128 * 32; c += 512) {
            int row = c >> 5, q = (c & 31) << 2;
            cpasync16(Zs + row * LZPITCH + q,
                      g_Z + ((size_t)(bm + row) * NT + t) * NG + bn + q);
        }
    };

    // ---- prologue (t = 0 reads zeroed g_hbuf[1]) ----
    issueB(0, 0); issueB(1, KC); issueA(0, 0, g_hbuf[1]); cp_commit();
    issueA(1, KC, g_hbuf[1]); cp_commit();

    const int NKT = NH / KC;   // 16

    #pragma unroll 1
    for (int t = 0; t < NT; t++) {
        const float* __restrict__ hsrc = g_hbuf[(t + 1) & 1];
        float* __restrict__ hdst = g_hbuf[t & 1];

        float acc[2][4][4];
        #pragma unroll
        for (int i = 0; i < 2; i++)
            #pragma unroll
            for (int j = 0; j < 4; j++)
                #pragma unroll
                for (int r = 0; r < 4; r++) acc[i][j][r] = 0.f;

        #pragma unroll 1
        for (int kt = 0; kt < NKT; kt++) {
            cp_wait1();               // drains the group holding slot kt
            __syncthreads();
            if (kt <= NKT - 3) {
                int s = (kt + 2) & (LSTAGES - 1);
                issueA(s, (kt + 2) * KC, hsrc);
                issueB(s, (kt + 2) * KC);
                if (kt == NKT - 3) issueZ(t);       // drained by kt=15's wait
            } else if (t < NT - 1) {
                int s = kt - (NKT - 2);             // 0, 1: next-step B prefetch
                issueB(s, s * KC);
            }
            cp_commit();

            // compute slot kt % LSTAGES
            uint32_t* As = sh + (kt & (LSTAGES - 1)) * LSTAGE_WORDS;
            uint32_t* Bs = As + 128 * SPAD;
            #pragma unroll
            for (int k8 = 0; k8 < KC; k8 += 8) {
                uint32_t a[2][4], b[4][2];
                #pragma unroll
                for (int mf = 0; mf < 2; mf++) {
                    int rb = wm + mf * 16;
                    a[mf][0] = As[(rb + gid) * SPAD + k8 + tg];
                    a[mf][1] = As[(rb + gid + 8) * SPAD + k8 + tg];
                    a[mf][2] = As[(rb + gid) * SPAD + k8 + tg + 4];
                    a[mf][3] = As[(rb + gid + 8) * SPAD + k8 + tg + 4];
                }
                #pragma unroll
                for (int nf = 0; nf < 4; nf++) {
                    int cb = wn + nf * 8;
                    b[nf][0] = Bs[(cb + gid) * SPAD + k8 + tg];
                    b[nf][1] = Bs[(cb + gid) * SPAD + k8 + tg + 4];
                }
                #pragma unroll
                for (int mf = 0; mf < 2; mf++)
                    #pragma unroll
                    for (int nf = 0; nf < 4; nf++)
                        mma_tf32(acc[mf][nf], a[mf], b[nf]);
            }
        }

        // ---- fused LSTM epilogue (Z + bias already in smem Z tile) ----
        const uint32_t* Zs = sh + LZOFF;
        #pragma unroll
        for (int nf = 0; nf < 4; nf++) {
            int nloc = wn + nf * 8 + 2 * tg;        // local col (even)
            int nblk = bn + wn + nf * 8;
            int hidx = (nblk >> 2) + (tg >> 1);
            #pragma unroll
            for (int mf = 0; mf < 2; mf++) {
                int rloc0 = wm + mf * 16 + gid;
                #pragma unroll
                for (int hh = 0; hh < 2; hh++) {
                    int rloc = rloc0 + hh * 8;
                    float2 zv = *(const float2*)(Zs + rloc * LZPITCH + nloc);
                    float v0 = acc[mf][nf][hh * 2 + 0] + zv.x;
                    float v1 = acc[mf][nf][hh * 2 + 1] + zv.y;
                    float p0 = __shfl_xor_sync(0xffffffffu, v0, 1);
                    float p1 = __shfl_xor_sync(0xffffffffu, v1, 1);
                    if (evn) {
                        float iv = sigmoidf_(v0);
                        float fv = sigmoidf_(v1);
                        float gv = tanhf_(p0);
                        float ov = sigmoidf_(p1);
                        int brow = bm + rloc;
                        int ci = brow * NH + hidx;
                        float cn = fv * g_cbuf[ci] + iv * gv;
                        float hn = ov * tanhf_(cn);
                        g_cbuf[ci] = cn;
                        hdst[ci] = __uint_as_float(f2tf32(hn));  // tf32 for next step
                        out[(size_t)brow * (NT * NH) + (size_t)t * NH + hidx] = hn;
                    }
                }
            }
        }

        // ---- per-group step barrier + next-step A refill ----
        if (t < NT - 1) {
            __threadfence();          // release h/c writes device-wide
            __syncthreads();          // all threads' writes + fences done
            if (tid == 0) {
                atomicAdd(&g_gbar[grp], 1);
                int target = 16 * (t + 1);          // monotonic, no reset race
                while (*(volatile int*)&g_gbar[grp] < target) { }
                __threadfence();      // acquire peers' h writes
            }
            __syncthreads();
            const float* __restrict__ hn = g_hbuf[t & 1];
            issueA(0, 0, hn); cp_commit();
            issueA(1, KC, hn); cp_commit();
        }
    }
}

extern "C" void kernel_launch(void* const* d_in, const int* in_sizes, int n_in,
                              void* d_out, int out_size) {
    const float* x    = (const float*)d_in[0]; // input_context [1024,64,512]
    const float* W    = (const float*)d_in[1]; // kernel [512,2048]
    const float* R    = (const float*)d_in[2]; // recurrent_kernel [512,2048]
    const float* bias = (const float*)d_in[3]; // bias [2048]
    float* out = (float*)d_out;                // [1024,64,512]

    cudaFuncSetAttribute(zgemm_kernel, cudaFuncAttributeMaxDynamicSharedMemorySize, ZSMEM);
    cudaFuncSetAttribute(lstm_persist, cudaFuncAttributeMaxDynamicSharedMemorySize, LSMEM);

    prep_kernel<<<512, 256>>>(W, R, bias);
    zgemm_kernel<<<dim3(16, 512), 256, ZSMEM>>>(x);
    lstm_persist<<<dim3(16, 8), 512, LSMEM>>>(out);
}